// round 3
// baseline (speedup 1.0000x reference)
#include <cuda_runtime.h>
#include <cstdint>

#define NN 200000
#define CH 128
#define KK 27
#define DD 3
#define CC (CH*CH)                  // 16384
#define WBLK (DD*KK)                // 81
#define SB 1024                     // stat blocks
#define TILE_M 128
#define NTIL ((NN + TILE_M - 1)/TILE_M)   // 1563
#define QMAX 32500.0f

// ---------------- device scratch (static) ----------------
__device__ __align__(16) int8_t g_xqh[(size_t)(NN+1)*CH];
__device__ __align__(16) int8_t g_xql[(size_t)(NN+1)*CH];
__device__ __align__(16) int8_t g_hqh[(size_t)(NN+1)*CH];
__device__ __align__(16) int8_t g_hql[(size_t)(NN+1)*CH];
__device__ __align__(16) int8_t g_wqh[(size_t)2*WBLK*CC];
__device__ __align__(16) int8_t g_wql[(size_t)2*WBLK*CC];
__device__ __align__(16) int8_t g_lqh[CC];
__device__ __align__(16) int8_t g_lql[CC];
__device__ __align__(16) float g_hbuf[(size_t)NN*CH];
__device__ __align__(16) float g_ybuf[(size_t)NN*CH];
__device__ float g_ps[SB*CH], g_pq[SB*CH], g_pmn[SB*CH], g_pmx[SB*CH];
__device__ float g_pmax[SB];
__device__ float g_sum[CH], g_sq[CH], g_r[CH];
// scale pairs: [0]=quant mult (QMAX/max), [1]=dequant step (max/QMAX)
__device__ float g_scx[2], g_sch[2], g_scw[2], g_scl[2], g_scxo[2];

// ---------------- helpers ----------------
__device__ __forceinline__ void quant16(float v, float qs, int8_t& h, int8_t& l) {
    int q = __float2int_rn(v * qs);
    int hh = (q + 128) >> 8;          // floor((q+128)/256) -> h in [-128,127]
    h = (int8_t)hh;
    l = (int8_t)(q - (hh << 8));      // l in [-128,127]
}

__device__ __forceinline__ void imma(int* d, const uint32_t* a, const uint32_t* b) {
    asm volatile(
        "mma.sync.aligned.m16n8k32.row.col.s32.s8.s8.s32 "
        "{%0,%1,%2,%3},{%4,%5,%6,%7},{%8,%9},{%0,%1,%2,%3};"
        : "+r"(d[0]), "+r"(d[1]), "+r"(d[2]), "+r"(d[3])
        : "r"(a[0]), "r"(a[1]), "r"(a[2]), "r"(a[3]), "r"(b[0]), "r"(b[1]));
}

// ---------------- max-abs reductions (deterministic) ----------------
__global__ void maxabs_kernel(const float* __restrict__ a, long n, int off) {
    __shared__ float sm[256];
    float m = 0.f;
    for (long i = (long)blockIdx.x*256 + threadIdx.x; i < n; i += (long)gridDim.x*256)
        m = fmaxf(m, fabsf(a[i]));
    sm[threadIdx.x] = m; __syncthreads();
    for (int s = 128; s > 0; s >>= 1) {
        if (threadIdx.x < s) sm[threadIdx.x] = fmaxf(sm[threadIdx.x], sm[threadIdx.x + s]);
        __syncthreads();
    }
    if (!threadIdx.x) g_pmax[off + blockIdx.x] = sm[0];
}

__global__ void reduce_scale_kernel(int cnt, float* sc) {
    __shared__ float sm[256];
    float m = 0.f;
    for (int i = threadIdx.x; i < cnt; i += 256) m = fmaxf(m, g_pmax[i]);
    sm[threadIdx.x] = m; __syncthreads();
    for (int s = 128; s > 0; s >>= 1) {
        if (threadIdx.x < s) sm[threadIdx.x] = fmaxf(sm[threadIdx.x], sm[threadIdx.x + s]);
        __syncthreads();
    }
    if (!threadIdx.x) {
        float mm = sm[0];
        if (mm < 1e-30f) { sc[0] = 0.f; sc[1] = 0.f; }
        else { sc[0] = QMAX / mm; sc[1] = mm / QMAX; }
    }
}

// ---------------- weight quant + transpose: [ci][co] -> [co][ci] ----------------
__global__ void split_w_kernel(const float* __restrict__ w1, const float* __restrict__ w2) {
    size_t i = (size_t)blockIdx.x*256 + threadIdx.x;
    if (i >= (size_t)2*WBLK*CC) return;
    size_t blk = i >> 14;
    int j = (int)(i & (CC-1));
    int ci = j >> 7, co = j & 127;
    float v = (blk < WBLK) ? w1[blk*CC + j] : w2[(blk - (size_t)WBLK)*CC + j];
    size_t dst = blk*CC + (size_t)co*CH + ci;
    quant16(v, g_scw[0], g_wqh[dst], g_wql[dst]);
}

__global__ void split_lin_kernel(const float* __restrict__ wlin) {
    int i = blockIdx.x*256 + threadIdx.x;
    if (i >= CC) return;
    int ci = i >> 7, co = i & 127;
    float v = wlin[(size_t)ci*CH + co];
    quant16(v, g_scl[0], g_lqh[(size_t)co*CH + ci], g_lql[(size_t)co*CH + ci]);
}

// ---------------- generic activation quantizer (sentinel row NN = 0) ----------------
__global__ void quant_kernel(const float* __restrict__ src, const float* __restrict__ sc,
                             int8_t* __restrict__ dh, int8_t* __restrict__ dl) {
    size_t i = (size_t)blockIdx.x*256 + threadIdx.x;
    if (i >= (size_t)(NN+1)*CH) return;
    float v = (i < (size_t)NN*CH) ? src[i] : 0.f;
    quant16(v, sc[0], dh[i], dl[i]);
}

// ---------------- int8 sparse conv: gather + 27 taps, dual-plane fixed point ----------------
// smem: AH[128*144] AL WH WL + sidx
__global__ void __launch_bounds__(256, 1)
conv_q_kernel(const int8_t* __restrict__ Ah, const int8_t* __restrict__ Al,
              const int8_t* __restrict__ Wh, const int8_t* __restrict__ Wl,
              const int* __restrict__ nbr, int ntaps, const float* __restrict__ bias,
              const float* __restrict__ dA, const float* __restrict__ dW,
              float* __restrict__ outp)
{
    extern __shared__ int8_t smem[];
    int8_t* AH = smem;
    int8_t* AL = smem + 18432;
    int8_t* WH = smem + 36864;
    int8_t* WL = smem + 55296;
    int* sidx = (int*)(smem + 73728);

    const int tid = threadIdx.x, lane = tid & 31, warp = tid >> 5;
    const int wm = warp >> 2, wn = warp & 3;        // 2 x 4 warp grid, 64x32 per warp
    const int gr = lane >> 2;                       // group row 0..7
    const int tg = (lane & 3) * 4;                  // 4-byte k-offset
    const int row0 = blockIdx.x * TILE_M;

    int ahh[4][4][4], acx[4][4][4];
    #pragma unroll
    for (int a = 0; a < 4; a++)
        #pragma unroll
        for (int b = 0; b < 4; b++)
            #pragma unroll
            for (int c = 0; c < 4; c++) { ahh[a][b][c] = 0; acx[a][b][c] = 0; }

    #pragma unroll 1
    for (int k = 0; k < ntaps; ++k) {
        __syncthreads();
        if (tid < 128) {
            int r = row0 + tid;
            sidx[tid] = (r < NN) ? (nbr ? nbr[(size_t)k*NN + r] : r) : NN;
        }
        __syncthreads();
        const uint4* wkh = (const uint4*)(Wh + (size_t)k*CC);
        const uint4* wkl = (const uint4*)(Wl + (size_t)k*CC);
        #pragma unroll
        for (int p = 0; p < 4; ++p) {
            int i = tid + p*256;                // 0..1023
            int row = i >> 3, seg = (i & 7) * 16;
            *(uint4*)(WH + row*144 + seg) = wkh[i];
            *(uint4*)(WL + row*144 + seg) = wkl[i];
            size_t src = (size_t)sidx[row]*CH + seg;
            *(uint4*)(AH + row*144 + seg) = *(const uint4*)(Ah + src);
            *(uint4*)(AL + row*144 + seg) = *(const uint4*)(Al + src);
        }
        __syncthreads();

        #pragma unroll
        for (int kc = 0; kc < 4; ++kc) {
            const int kb = kc*32;
            uint32_t aH[4][4], aL[4][4], bH[4][2], bL[4][2];
            #pragma unroll
            for (int mi = 0; mi < 4; ++mi) {
                int rb = wm*64 + mi*16 + gr;
                int o0 = rb*144 + kb + tg;
                int o1 = (rb+8)*144 + kb + tg;
                aH[mi][0] = *(const uint32_t*)(AH + o0);
                aH[mi][1] = *(const uint32_t*)(AH + o1);
                aH[mi][2] = *(const uint32_t*)(AH + o0 + 16);
                aH[mi][3] = *(const uint32_t*)(AH + o1 + 16);
                aL[mi][0] = *(const uint32_t*)(AL + o0);
                aL[mi][1] = *(const uint32_t*)(AL + o1);
                aL[mi][2] = *(const uint32_t*)(AL + o0 + 16);
                aL[mi][3] = *(const uint32_t*)(AL + o1 + 16);
            }
            #pragma unroll
            for (int ni = 0; ni < 4; ++ni) {
                int nr = wn*32 + ni*8 + gr;
                int o = nr*144 + kb + tg;
                bH[ni][0] = *(const uint32_t*)(WH + o);
                bH[ni][1] = *(const uint32_t*)(WH + o + 16);
                bL[ni][0] = *(const uint32_t*)(WL + o);
                bL[ni][1] = *(const uint32_t*)(WL + o + 16);
            }
            #pragma unroll
            for (int mi = 0; mi < 4; ++mi)
                #pragma unroll
                for (int ni = 0; ni < 4; ++ni) {
                    imma(ahh[mi][ni], aH[mi], bH[ni]);   // 65536 term
                    imma(acx[mi][ni], aH[mi], bL[ni]);   // 256 term
                    imma(acx[mi][ni], aL[mi], bH[ni]);   // 256 term
                }
        }
    }

    const float d = dA[1] * dW[1];
    #pragma unroll
    for (int mi = 0; mi < 4; ++mi) {
        int r0 = row0 + wm*64 + mi*16 + gr;
        #pragma unroll
        for (int ni = 0; ni < 4; ++ni) {
            int col = wn*32 + ni*8 + (lane & 3)*2;
            float v0 = d * (65536.f*(float)ahh[mi][ni][0] + 256.f*(float)acx[mi][ni][0]);
            float v1 = d * (65536.f*(float)ahh[mi][ni][1] + 256.f*(float)acx[mi][ni][1]);
            float v2 = d * (65536.f*(float)ahh[mi][ni][2] + 256.f*(float)acx[mi][ni][2]);
            float v3 = d * (65536.f*(float)ahh[mi][ni][3] + 256.f*(float)acx[mi][ni][3]);
            if (bias) {
                float b0 = bias[col], b1 = bias[col+1];
                v0 += b0; v1 += b1; v2 += b0; v3 += b1;
            }
            if (r0 < NN)     *(float2*)&outp[(size_t)r0*CH + col]     = make_float2(v0, v1);
            if (r0 + 8 < NN) *(float2*)&outp[(size_t)(r0+8)*CH + col] = make_float2(v2, v3);
        }
    }
}

// ---------------- BN stats (sum, sumsq, min, max per channel) ----------------
__global__ void stats_kernel(const float* __restrict__ h) {
    int c = threadIdx.x;
    float s = 0.f, q = 0.f, mn = 1e30f, mx = -1e30f;
    for (int r = blockIdx.x; r < NN; r += SB) {
        float v = h[(size_t)r*CH + c];
        s += v; q += v*v;
        mn = fminf(mn, v); mx = fmaxf(mx, v);
    }
    g_ps[blockIdx.x*CH + c] = s;
    g_pq[blockIdx.x*CH + c] = q;
    g_pmn[blockIdx.x*CH + c] = mn;
    g_pmx[blockIdx.x*CH + c] = mx;
}

// reduce; when sc != null also derive bn-output quant scale from per-channel extremes
__global__ void reduce_kernel(const float* __restrict__ g, const float* __restrict__ b,
                              float* sc) {
    int c = threadIdx.x;
    float s = 0.f, q = 0.f, mn = 1e30f, mx = -1e30f;
    for (int i = 0; i < SB; ++i) {
        s += g_ps[i*CH + c]; q += g_pq[i*CH + c];
        mn = fminf(mn, g_pmn[i*CH + c]); mx = fmaxf(mx, g_pmx[i*CH + c]);
    }
    g_sum[c] = s; g_sq[c] = q;
    if (sc) {
        float m = s * (1.f/NN);
        float var = q * (1.f/NN) - m*m;
        float scale = g[c] * rsqrtf(var + 1e-5f);
        float v1 = (mn - m)*scale + b[c];
        float v2 = (mx - m)*scale + b[c];
        float chm = fmaxf(fmaxf(v1, v2), 0.f);   // post-relu max
        __shared__ float smx[128];
        smx[c] = chm; __syncthreads();
        for (int st = 64; st > 0; st >>= 1) {
            if (c < st) smx[c] = fmaxf(smx[c], smx[c + st]);
            __syncthreads();
        }
        if (!c) {
            float mm = smx[0];
            if (mm < 1e-30f) { sc[0] = 0.f; sc[1] = 0.f; }
            else { sc[0] = QMAX / mm; sc[1] = mm / QMAX; }
        }
    }
}

// ---------------- BN + ReLU + int8 dual-plane quant ----------------
__global__ void bn_relu_quant_kernel(const float* __restrict__ h,
                                     const float* __restrict__ g, const float* __restrict__ b) {
    size_t i = (size_t)blockIdx.x*256 + threadIdx.x;
    if (i >= (size_t)(NN+1)*CH) return;
    int c = (int)(i & (CH-1));
    float val = 0.f;
    if (i < (size_t)NN*CH) {
        float m = g_sum[c] * (1.f/NN);
        float v = g_sq[c] * (1.f/NN) - m*m;
        float scale = g[c] * rsqrtf(v + 1e-5f);
        val = fmaxf((h[i] - m)*scale + b[c], 0.f);
    }
    quant16(val, g_sch[0], g_hqh[i], g_hql[i]);
}

// ---------------- BN + accumulate into y ----------------
__global__ void bn_acc_kernel(const float* __restrict__ h,
                              const float* __restrict__ g, const float* __restrict__ b,
                              int first) {
    size_t i = (size_t)blockIdx.x*256 + threadIdx.x;
    if (i >= (size_t)NN*CH) return;
    int c = (int)(i & (CH-1));
    float m = g_sum[c] * (1.f/NN);
    float v = g_sq[c] * (1.f/NN) - m*m;
    float scale = g[c] * rsqrtf(v + 1e-5f);
    float bnv = (h[i] - m)*scale + b[c];
    g_ybuf[i] = first ? bnv : (g_ybuf[i] + bnv);
}

// ---------------- xout = relu(y + x): store fp32, col sums, block max ----------------
__global__ void relu_add_kernel(const float* __restrict__ x) {
    int c = threadIdx.x;
    float s = 0.f, mx = 0.f;
    for (int r = blockIdx.x; r < NN; r += SB) {
        size_t i = (size_t)r*CH + c;
        float v = fmaxf(g_ybuf[i] + x[i], 0.f);
        g_hbuf[i] = v;
        s += v; mx = fmaxf(mx, v);
    }
    g_ps[blockIdx.x*CH + c] = s;
    __shared__ float smx[128];
    smx[c] = mx; __syncthreads();
    for (int st = 64; st > 0; st >>= 1) {
        if (c < st) smx[c] = fmaxf(smx[c], smx[c + st]);
        __syncthreads();
    }
    if (!c) g_pmax[blockIdx.x] = smx[0];
}

__global__ void reduce_xo_kernel() {
    int c = threadIdx.x;
    float s = 0.f;
    for (int i = 0; i < SB; ++i) s += g_ps[i*CH + c];
    g_sum[c] = s;
    float m = 0.f;
    for (int i = c; i < SB; i += 128) m = fmaxf(m, g_pmax[i]);
    __shared__ float smx[128];
    smx[c] = m; __syncthreads();
    for (int st = 64; st > 0; st >>= 1) {
        if (c < st) smx[c] = fmaxf(smx[c], smx[c + st]);
        __syncthreads();
    }
    if (!c) {
        float mm = smx[0];
        if (mm < 1e-30f) { g_scxo[0] = 0.f; g_scxo[1] = 0.f; }
        else { g_scxo[0] = QMAX / mm; g_scxo[1] = mm / QMAX; }
    }
}

// ---------------- r = mean(xout) @ Wb + blin ----------------
__global__ void make_r_kernel(const float* __restrict__ wlin, const float* __restrict__ blin) {
    int co = threadIdx.x;
    float acc = blin[co];
    for (int ci = 0; ci < CH; ++ci)
        acc += (g_sum[ci] * (1.f/NN)) * wlin[(size_t)(CH + ci)*CH + co];
    g_r[co] = acc;
}

// ---------------- launch ----------------
extern "C" void kernel_launch(void* const* d_in, const int* in_sizes, int n_in,
                              void* d_out, int out_size) {
    const float* x    = (const float*)d_in[0];
    const float* w1   = (const float*)d_in[1];
    const float* w2   = (const float*)d_in[2];
    const float* g1   = (const float*)d_in[3];
    const float* b1   = (const float*)d_in[4];
    const float* g2   = (const float*)d_in[5];
    const float* b2   = (const float*)d_in[6];
    const float* wlin = (const float*)d_in[7];
    const float* blin = (const float*)d_in[8];
    const int*   nbr  = (const int*)d_in[9];
    float* outp = (float*)d_out;

    const int SMEM = 73728 + 512;
    static int smem_set = 0;
    cudaFuncSetAttribute(conv_q_kernel, cudaFuncAttributeMaxDynamicSharedMemorySize, SMEM);
    (void)smem_set;

    int8_t *xh, *xl, *hh, *hl, *wh, *wl, *lh, *ll;
    float *h, *rptr, *scx, *sch, *scw, *scl, *scxo;
    cudaGetSymbolAddress((void**)&xh, g_xqh);
    cudaGetSymbolAddress((void**)&xl, g_xql);
    cudaGetSymbolAddress((void**)&hh, g_hqh);
    cudaGetSymbolAddress((void**)&hl, g_hql);
    cudaGetSymbolAddress((void**)&wh, g_wqh);
    cudaGetSymbolAddress((void**)&wl, g_wql);
    cudaGetSymbolAddress((void**)&lh, g_lqh);
    cudaGetSymbolAddress((void**)&ll, g_lql);
    cudaGetSymbolAddress((void**)&h,  g_hbuf);
    cudaGetSymbolAddress((void**)&rptr, g_r);
    cudaGetSymbolAddress((void**)&scx,  g_scx);
    cudaGetSymbolAddress((void**)&sch,  g_sch);
    cudaGetSymbolAddress((void**)&scw,  g_scw);
    cudaGetSymbolAddress((void**)&scl,  g_scl);
    cudaGetSymbolAddress((void**)&scxo, g_scxo);

    size_t nq = (size_t)(NN+1)*CH;
    int qgrid = (int)((nq + 255)/256);

    // scales
    maxabs_kernel<<<512, 256>>>(x, (long)NN*CH, 0);
    reduce_scale_kernel<<<1, 256>>>(512, scx);
    maxabs_kernel<<<256, 256>>>(w1, (long)WBLK*CC, 0);
    maxabs_kernel<<<256, 256>>>(w2, (long)WBLK*CC, 256);
    reduce_scale_kernel<<<1, 256>>>(512, scw);
    maxabs_kernel<<<128, 256>>>(wlin, (long)CC, 0);
    reduce_scale_kernel<<<1, 256>>>(128, scl);

    // quantize weights + x
    split_w_kernel<<<(int)((2ull*WBLK*CC + 255)/256), 256>>>(w1, w2);
    split_lin_kernel<<<(CC + 255)/256, 256>>>(wlin);
    quant_kernel<<<qgrid, 256>>>(x, scx, xh, xl);

    for (int d = 0; d < DD; ++d) {
        const int* nb = nbr + (size_t)d*KK*NN;
        conv_q_kernel<<<NTIL, 256, SMEM>>>(xh, xl,
            wh + (size_t)d*KK*CC, wl + (size_t)d*KK*CC, nb, KK, nullptr, scx, scw, h);
        stats_kernel<<<SB, CH>>>(h);
        reduce_kernel<<<1, CH>>>(g1 + d*CH, b1 + d*CH, sch);
        bn_relu_quant_kernel<<<qgrid, 256>>>(h, g1 + d*CH, b1 + d*CH);
        conv_q_kernel<<<NTIL, 256, SMEM>>>(hh, hl,
            wh + (size_t)(WBLK + d*KK)*CC, wl + (size_t)(WBLK + d*KK)*CC, nb, KK, nullptr, sch, scw, h);
        stats_kernel<<<SB, CH>>>(h);
        reduce_kernel<<<1, CH>>>(g2 + d*CH, b2 + d*CH, nullptr);
        bn_acc_kernel<<<(int)(((size_t)NN*CH + 255)/256), 256>>>(h, g2 + d*CH, b2 + d*CH, d == 0);
    }

    relu_add_kernel<<<SB, CH>>>(x);
    reduce_xo_kernel<<<1, CH>>>();
    make_r_kernel<<<1, CH>>>(wlin, blin);
    quant_kernel<<<qgrid, 256>>>(h, scxo, hh, hl);
    conv_q_kernel<<<NTIL, 256, SMEM>>>(hh, hl, lh, ll, nullptr, 1, rptr, scxo, scl, outp);
}